// round 2
// baseline (speedup 1.0000x reference)
#include <cuda_runtime.h>
#include <math.h>

// Problem shapes (fixed for this dataset entry)
#define B_    16
#define CH    512
#define HDIM  128
#define WDIM  128
#define HW    (HDIM*WDIM)     // 16384
#define C_    16              // selected classes
#define G_    (CH/C_)         // 32 groups
#define NP    120             // C*(C-1)/2 off-diagonal pairs
#define S_    2               // HW chunks per (b,g)
#define CHUNK (HW/S_)         // 8192
#define NBG   (B_*G_)         // 512
#define THREADS 256

// Scratch (static __device__ — no allocations allowed)
__device__ int   d_src[CH];              // [g*C_+j] -> source channel in x
__device__ float d_wgh[CH];              // [g*C_+j] -> sigmoid(|w|)
__device__ float d_part[NBG*S_*NP];      // partial Gram sums
__device__ float d_bgsum[NBG];           // per-(b,g) weighted |off| sums

__device__ __forceinline__ int pair_index(int i, int j) {
    // i<j, row-major over upper triangle
    return i*C_ - (i*(i+1))/2 + (j - i - 1);
}

// ---------------------------------------------------------------------------
// Kernel 1: per-class top-G selection of |W| (stable: lower index wins ties)
// One warp per selected class. 512 threads = 16 warps.
// ---------------------------------------------------------------------------
__global__ void prep_kernel(const float* __restrict__ cw, const int* __restrict__ sel) {
    int warp = threadIdx.x >> 5;
    int lane = threadIdx.x & 31;
    if (warp >= C_) return;
    int cls = sel[warp];

    // lane holds channels t*32+lane, t=0..15, in registers
    float v[CH/32];
#pragma unroll
    for (int t = 0; t < CH/32; t++)
        v[t] = fabsf(cw[cls*CH + t*32 + lane]);

    for (int k = 0; k < G_; k++) {
        // local argmax (first occurrence = lowest index since idx grows with t)
        float bv = -1.0f; int bi = CH;
#pragma unroll
        for (int t = 0; t < CH/32; t++) {
            int idx = t*32 + lane;
            if (v[t] > bv || (v[t] == bv && idx < bi)) { bv = v[t]; bi = idx; }
        }
        // warp argmax with lower-index tie-break
#pragma unroll
        for (int off = 16; off > 0; off >>= 1) {
            float ov = __shfl_down_sync(0xffffffffu, bv, off);
            int   oi = __shfl_down_sync(0xffffffffu, bi, off);
            if (ov > bv || (ov == bv && oi < bi)) { bv = ov; bi = oi; }
        }
        bv = __shfl_sync(0xffffffffu, bv, 0);
        bi = __shfl_sync(0xffffffffu, bi, 0);
        // consume the winner
        if ((bi & 31) == lane) v[bi >> 5] = -1.0f;
        if (lane == 0) {
            d_src[k*C_ + warp] = bi;
            d_wgh[k*C_ + warp] = 1.0f / (1.0f + expf(-bv));
        }
    }
}

// ---------------------------------------------------------------------------
// Kernel 2: partial Gram per (b, g, chunk). 120 fp32 accumulators/thread,
// float2 loads (16 per iter) for MLP. Writes 120 partials per CTA (no atomics).
// ---------------------------------------------------------------------------
__global__ void __launch_bounds__(THREADS, 1)
gram_kernel(const float* __restrict__ x) {
    int bid = blockIdx.x;                 // 0 .. NBG*S_-1
    int bg  = bid >> 1;                   // S_ == 2
    int s   = bid & (S_-1);
    int b   = bg / G_;
    int g   = bg % G_;

    __shared__ int src[C_];
    if (threadIdx.x < C_) src[threadIdx.x] = d_src[g*C_ + threadIdx.x];
    __syncthreads();

    const float2* p[C_];
#pragma unroll
    for (int i = 0; i < C_; i++)
        p[i] = (const float2*)(x + ((size_t)(b*CH + src[i]))*HW + (size_t)s*CHUNK);

    float acc[NP];
#pragma unroll
    for (int q = 0; q < NP; q++) acc[q] = 0.0f;

    for (int it = threadIdx.x; it < CHUNK/2; it += THREADS) {
        float2 v[C_];
#pragma unroll
        for (int i = 0; i < C_; i++) v[i] = p[i][it];
#pragma unroll
        for (int i = 0; i < C_; i++)
#pragma unroll
            for (int j = i+1; j < C_; j++)
                acc[pair_index(i,j)] += v[i].x*v[j].x + v[i].y*v[j].y;
    }

    // warp reduce all 120 accumulators
#pragma unroll
    for (int q = 0; q < NP; q++) {
        float a = acc[q];
#pragma unroll
        for (int off = 16; off > 0; off >>= 1)
            a += __shfl_down_sync(0xffffffffu, a, off);
        acc[q] = a;
    }

    __shared__ float red[THREADS/32][NP];
    int warp = threadIdx.x >> 5;
    int lane = threadIdx.x & 31;
    if (lane == 0) {
#pragma unroll
        for (int q = 0; q < NP; q++) red[warp][q] = acc[q];
    }
    __syncthreads();
    if (threadIdx.x < NP) {
        float sum = 0.0f;
#pragma unroll
        for (int w = 0; w < THREADS/32; w++) sum += red[w][threadIdx.x];
        d_part[(size_t)bid*NP + threadIdx.x] = sum;
    }
}

// ---------------------------------------------------------------------------
// Kernel 3: combine chunks, apply |.| * w_i * w_j, reduce per (b,g)
// ---------------------------------------------------------------------------
__global__ void pair_kernel() {
    int bg = blockIdx.x;
    int p  = threadIdx.x;
    float val = 0.0f;
    if (p < NP) {
        float dot = 0.0f;
#pragma unroll
        for (int s = 0; s < S_; s++)
            dot += d_part[((size_t)bg*S_ + s)*NP + p];
        // decode (i,j) from p
        int i = 0, rem = p;
        while (rem >= (C_-1-i)) { rem -= (C_-1-i); i++; }
        int j = i + 1 + rem;
        int g = bg % G_;
        val = fabsf(dot) * d_wgh[g*C_ + i] * d_wgh[g*C_ + j];
    }
    __shared__ float sm[128];
    sm[threadIdx.x] = val;
    __syncthreads();
#pragma unroll
    for (int off = 64; off > 0; off >>= 1) {
        if (threadIdx.x < off) sm[threadIdx.x] += sm[threadIdx.x + off];
        __syncthreads();
    }
    if (threadIdx.x == 0) d_bgsum[bg] = sm[0];
}

// ---------------------------------------------------------------------------
// Kernel 4: final reduce + normalization
// loss = sum / ((HW-1) * NP * B)
// ---------------------------------------------------------------------------
__global__ void final_kernel(float* __restrict__ out) {
    __shared__ float sm[NBG];
    sm[threadIdx.x] = d_bgsum[threadIdx.x];
    __syncthreads();
#pragma unroll
    for (int off = NBG/2; off > 0; off >>= 1) {
        if (threadIdx.x < off) sm[threadIdx.x] += sm[threadIdx.x + off];
        __syncthreads();
    }
    if (threadIdx.x == 0)
        out[0] = sm[0] * (1.0f / ((float)(HW-1) * (float)NP * (float)B_));
}

extern "C" void kernel_launch(void* const* d_in, const int* in_sizes, int n_in,
                              void* d_out, int out_size) {
    const float* x   = (const float*)d_in[0];
    const float* cw  = (const float*)d_in[1];
    const int*   sel = (const int*)d_in[2];
    float* out = (float*)d_out;

    prep_kernel<<<1, 512>>>(cw, sel);
    gram_kernel<<<NBG*S_, THREADS>>>(x);
    pair_kernel<<<NBG, 128>>>();
    final_kernel<<<1, NBG>>>(out);
}

// round 3
// speedup vs baseline: 1.0498x; 1.0498x over previous
#include <cuda_runtime.h>
#include <math.h>

// Problem shapes (fixed for this dataset entry)
#define B_    16
#define CH    512
#define HDIM  128
#define WDIM  128
#define HW    (HDIM*WDIM)     // 16384
#define C_    16              // selected classes
#define G_    (CH/C_)         // 32 groups
#define NP    120             // C*(C-1)/2 off-diagonal pairs
#define S_    2               // HW chunks per (b,g)
#define CHUNK (HW/S_)         // 8192
#define NBG   (B_*G_)         // 512
#define THREADS 256

// Scratch (static __device__ — no allocations allowed)
__device__ int   d_src[CH];              // [g*C_+j] -> source channel in x
__device__ float d_wgh[CH];              // [g*C_+j] -> sigmoid(|w|)
__device__ float d_pw[G_*NP];            // [g*NP+p] -> w_i * w_j for pair p
__device__ float d_part[NBG*S_*NP];      // partial Gram sums

__device__ __forceinline__ int pair_index(int i, int j) {
    return i*C_ - (i*(i+1))/2 + (j - i - 1);
}

// ---------------------------------------------------------------------------
// Kernel 1: per-class top-G selection of |W| (stable: lower index wins ties)
// One warp per selected class (16 warps = 512 threads). Also precomputes the
// per-group pair weight products d_pw.
// ---------------------------------------------------------------------------
__global__ void prep_kernel(const float* __restrict__ cw, const int* __restrict__ sel) {
    int warp = threadIdx.x >> 5;
    int lane = threadIdx.x & 31;
    int cls = sel[warp];

    float v[CH/32];
#pragma unroll
    for (int t = 0; t < CH/32; t++)
        v[t] = fabsf(cw[cls*CH + t*32 + lane]);

    for (int k = 0; k < G_; k++) {
        float bv = -1.0f; int bi = CH;
#pragma unroll
        for (int t = 0; t < CH/32; t++) {
            int idx = t*32 + lane;
            if (v[t] > bv || (v[t] == bv && idx < bi)) { bv = v[t]; bi = idx; }
        }
#pragma unroll
        for (int off = 16; off > 0; off >>= 1) {
            float ov = __shfl_down_sync(0xffffffffu, bv, off);
            int   oi = __shfl_down_sync(0xffffffffu, bi, off);
            if (ov > bv || (ov == bv && oi < bi)) { bv = ov; bi = oi; }
        }
        bv = __shfl_sync(0xffffffffu, bv, 0);
        bi = __shfl_sync(0xffffffffu, bi, 0);
        if ((bi & 31) == lane) v[bi >> 5] = -1.0f;
        if (lane == 0) {
            d_src[k*C_ + warp] = bi;
            d_wgh[k*C_ + warp] = 1.0f / (1.0f + expf(-bv));
        }
    }
    __syncthreads();
    // pair-weight products: G_*NP = 3840 entries
    for (int idx = threadIdx.x; idx < G_*NP; idx += blockDim.x) {
        int g = idx / NP, p = idx % NP;
        int i = 0, rem = p;
        while (rem >= (C_-1-i)) { rem -= (C_-1-i); i++; }
        int j = i + 1 + rem;
        d_pw[idx] = d_wgh[g*C_ + i] * d_wgh[g*C_ + j];
    }
}

// ---------------------------------------------------------------------------
// Kernel 2: partial Gram per (b, g, chunk). 120 fp32 accumulators/thread.
// float4 streaming loads: 16 LDG.128 + 480 FFMA per iteration so compute
// issue per warp (~960 cyc) exceeds DRAM latency (~600 cyc) -> FFMA pipe
// saturates with 2 warps/SMSP. 32-bit channel offsets from one base pointer.
// ---------------------------------------------------------------------------
__global__ void __launch_bounds__(THREADS, 1)
gram_kernel(const float* __restrict__ x) {
    int bid = blockIdx.x;                 // 0 .. NBG*S_-1
    int bg  = bid >> 1;                   // S_ == 2
    int s   = bid & (S_-1);
    int b   = bg / G_;
    int g   = bg % G_;

    __shared__ int soff[C_];
    if (threadIdx.x < C_)
        soff[threadIdx.x] = d_src[g*C_ + threadIdx.x] * (HW/4);  // float4 units
    __syncthreads();

    const float4* base = (const float4*)x + ((size_t)b * CH) * (HW/4) + (size_t)s * (CHUNK/4);
    int off[C_];
#pragma unroll
    for (int i = 0; i < C_; i++) off[i] = soff[i];

    float acc[NP];
#pragma unroll
    for (int q = 0; q < NP; q++) acc[q] = 0.0f;

    for (int it = threadIdx.x; it < CHUNK/4; it += THREADS) {
        float4 v[C_];
#pragma unroll
        for (int i = 0; i < C_; i++) v[i] = __ldcs(base + off[i] + it);
#pragma unroll
        for (int i = 0; i < C_; i++) {
#pragma unroll
            for (int j = i+1; j < C_; j++) {
                int q = pair_index(i,j);
                acc[q] += v[i].x*v[j].x;
                acc[q] += v[i].y*v[j].y;
                acc[q] += v[i].z*v[j].z;
                acc[q] += v[i].w*v[j].w;
            }
        }
    }

    // warp reduce all 120 accumulators
#pragma unroll
    for (int q = 0; q < NP; q++) {
        float a = acc[q];
#pragma unroll
        for (int off2 = 16; off2 > 0; off2 >>= 1)
            a += __shfl_down_sync(0xffffffffu, a, off2);
        acc[q] = a;
    }

    __shared__ float red[THREADS/32][NP];
    int warp = threadIdx.x >> 5;
    int lane = threadIdx.x & 31;
    if (lane == 0) {
#pragma unroll
        for (int q = 0; q < NP; q++) red[warp][q] = acc[q];
    }
    __syncthreads();
    if (threadIdx.x < NP) {
        float sum = 0.0f;
#pragma unroll
        for (int w = 0; w < THREADS/32; w++) sum += red[w][threadIdx.x];
        d_part[(size_t)bid*NP + threadIdx.x] = sum;
    }
}

// ---------------------------------------------------------------------------
// Kernel 3: fused combine + |.|*w_i*w_j + full reduction + normalization.
// One CTA, 512 threads: thread t owns (b,g)=t.
// ---------------------------------------------------------------------------
__global__ void reduce_kernel(float* __restrict__ out) {
    int bg = threadIdx.x;                 // 0..NBG-1
    int g  = bg % G_;
    const float* pa = d_part + (size_t)(2*bg)   * NP;
    const float* pb = d_part + (size_t)(2*bg+1) * NP;
    const float* pw = d_pw + g*NP;

    float sum = 0.0f;
#pragma unroll 8
    for (int p = 0; p < NP; p++)
        sum += fabsf(pa[p] + pb[p]) * pw[p];

    __shared__ float sm[NBG];
    sm[bg] = sum;
    __syncthreads();
#pragma unroll
    for (int off = NBG/2; off > 0; off >>= 1) {
        if (threadIdx.x < off) sm[threadIdx.x] += sm[threadIdx.x + off];
        __syncthreads();
    }
    if (threadIdx.x == 0)
        out[0] = sm[0] * (1.0f / ((float)(HW-1) * (float)NP * (float)B_));
}

extern "C" void kernel_launch(void* const* d_in, const int* in_sizes, int n_in,
                              void* d_out, int out_size) {
    const float* x   = (const float*)d_in[0];
    const float* cw  = (const float*)d_in[1];
    const int*   sel = (const int*)d_in[2];
    float* out = (float*)d_out;

    prep_kernel<<<1, 512>>>(cw, sel);
    gram_kernel<<<NBG*S_, THREADS>>>(x);
    reduce_kernel<<<1, NBG>>>(out);
}

// round 5
// speedup vs baseline: 1.0750x; 1.0239x over previous
#include <cuda_runtime.h>
#include <stdint.h>
#include <math.h>

// Problem shapes (fixed for this dataset entry)
#define B_    16
#define CH    512
#define HW    16384
#define C_    16              // selected classes
#define G_    32              // groups (CH/C_)
#define NP    120             // C*(C-1)/2 off-diagonal pairs
#define S_    2               // HW chunks per (b,g)
#define CHUNK (HW/S_)         // 8192
#define NBG   (B_*G_)         // 512
#define THREADS 256

#define SK        1024                  // floats per channel per stage
#define NSTAGES   (CHUNK/SK)            // 8
#define SMEM_FLOATS (2*C_*SK)           // 32768 floats = 128 KB

// Scratch (static __device__ — no allocations allowed)
__device__ int   d_src[CH];              // [k*C_+cls] -> source channel in x
__device__ float d_wgh[CH];              // [k*C_+cls] -> sigmoid(|w|)
__device__ float d_part[NBG*S_*NP];      // partial Gram sums

__device__ __forceinline__ void cp_async16(unsigned int saddr, const void* gptr) {
    asm volatile("cp.async.cg.shared.global [%0], [%1], 16;" :: "r"(saddr), "l"(gptr));
}
__device__ __forceinline__ void cp_commit() {
    asm volatile("cp.async.commit_group;");
}
template<int N>
__device__ __forceinline__ void cp_wait() {
    asm volatile("cp.async.wait_group %0;" :: "n"(N));
}
__device__ __forceinline__ unsigned int smem_u32(const void* p) {
    unsigned int a;
    asm("{ .reg .u64 t; cvta.to.shared.u64 t, %1; cvt.u32.u64 %0, t; }" : "=r"(a) : "l"(p));
    return a;
}

// ---------------------------------------------------------------------------
// Kernel 1: rank-based top-G selection. Grid = 16 CTAs (one per selected
// class), 512 threads (one per channel). rank(c) = #{d : |w_d|>|w_c| ||
// (|w_d|==|w_c| && d<c)}  == position in stable descending argsort.
// ---------------------------------------------------------------------------
__global__ void prep_kernel(const float* __restrict__ cw, const int* __restrict__ sel) {
    __shared__ float sm[CH];
    int t = threadIdx.x;
    int cls = sel[blockIdx.x];
    float val = fabsf(cw[cls*CH + t]);
    sm[t] = val;
    __syncthreads();

    int rank = 0;
#pragma unroll 8
    for (int d = 0; d < CH; d++) {
        float o = sm[d];
        rank += (o > val) || (o == val && d < t);
    }
    if (rank < G_) {
        d_src[rank*C_ + blockIdx.x] = t;
        d_wgh[rank*C_ + blockIdx.x] = 1.0f / (1.0f + expf(-val));
    }
}

// ---------------------------------------------------------------------------
// Kernel 2: partial Gram per (b, g, chunk) with cp.async double-buffered smem
// pipeline. Stage = 16 channels x 1024 floats (64 KB); 2 buffers; 8 stages.
// Each thread: 16 LDS.128 + 480 FFMA per stage into 120 accumulators.
// ---------------------------------------------------------------------------
extern __shared__ float sA[];   // [2][C_][SK]

__global__ void __launch_bounds__(THREADS, 1)
gram_kernel(const float* __restrict__ x) {
    int bid = blockIdx.x;                 // 0 .. NBG*S_-1
    int bg  = bid >> 1;                   // S_ == 2
    int s   = bid & (S_-1);
    int b   = bg / G_;
    int g   = bg % G_;
    int t   = threadIdx.x;

    __shared__ int soff[C_];
    if (t < C_)
        soff[t] = d_src[g*C_ + t] * (HW/4);  // channel offset in float4 units
    __syncthreads();

    const float4* base = (const float4*)x + ((size_t)b * CH) * (HW/4) + (size_t)s * (CHUNK/4);
    int off[C_];
#pragma unroll
    for (int i = 0; i < C_; i++) off[i] = soff[i];

    unsigned int sbase = smem_u32(sA);

    // copy stage 'st' into buffer 'buf': thread t copies float4 #t of each channel
    auto copy_stage = [&](int st, int buf) {
#pragma unroll
        for (int ch = 0; ch < C_; ch++) {
            unsigned int daddr = sbase + (unsigned int)(((buf*C_ + ch)*SK + 4*t) * 4);
            cp_async16(daddr, (const void*)(base + off[ch] + st*(SK/4) + t));
        }
        cp_commit();
    };

    float acc[NP];
#pragma unroll
    for (int q = 0; q < NP; q++) acc[q] = 0.0f;

    copy_stage(0, 0);

    for (int st = 0; st < NSTAGES; st++) {
        __syncthreads();                       // compute of st-1 done; safe to refill
        if (st + 1 < NSTAGES) { copy_stage(st + 1, (st + 1) & 1); cp_wait<1>(); }
        else                  { cp_wait<0>(); }
        __syncthreads();                       // stage st visible to all

        const float4* sp = (const float4*)(sA + ((st & 1) * C_) * SK) + t;
        float4 v[C_];
#pragma unroll
        for (int i = 0; i < C_; i++) v[i] = sp[i * (SK/4)];
        int q = 0;
#pragma unroll
        for (int i = 0; i < C_; i++) {
#pragma unroll
            for (int j = i+1; j < C_; j++) {
                acc[q] += v[i].x*v[j].x;
                acc[q] += v[i].y*v[j].y;
                acc[q] += v[i].z*v[j].z;
                acc[q] += v[i].w*v[j].w;
                q++;
            }
        }
    }

    // warp reduce all 120 accumulators
#pragma unroll
    for (int q = 0; q < NP; q++) {
        float a = acc[q];
#pragma unroll
        for (int o = 16; o > 0; o >>= 1)
            a += __shfl_down_sync(0xffffffffu, a, o);
        acc[q] = a;
    }

    __syncthreads();                           // done reading pipeline smem
    float* red = sA;                           // reuse smem: [8][NP]
    int warp = t >> 5, lane = t & 31;
    if (lane == 0) {
#pragma unroll
        for (int q = 0; q < NP; q++) red[warp*NP + q] = acc[q];
    }
    __syncthreads();
    if (t < NP) {
        float sum = 0.0f;
#pragma unroll
        for (int w = 0; w < THREADS/32; w++) sum += red[w*NP + t];
        d_part[(size_t)bid*NP + t] = sum;
    }
}

// ---------------------------------------------------------------------------
// Kernel 3: fused combine + |.|*w_i*w_j + full reduction + normalization.
// One CTA, 512 threads: thread t owns (b,g)=t. Pair weights computed inline.
// ---------------------------------------------------------------------------
__global__ void reduce_kernel(float* __restrict__ out) {
    int bg = threadIdx.x;                 // 0..NBG-1
    int g  = bg % G_;
    const float* pa = d_part + (size_t)(2*bg)   * NP;
    const float* pb = d_part + (size_t)(2*bg+1) * NP;

    float w[C_];
#pragma unroll
    for (int i = 0; i < C_; i++) w[i] = d_wgh[g*C_ + i];

    float sum = 0.0f;
    int p = 0;
#pragma unroll
    for (int i = 0; i < C_; i++) {
#pragma unroll
        for (int j = i+1; j < C_; j++) {
            sum += fabsf(pa[p] + pb[p]) * (w[i] * w[j]);
            p++;
        }
    }

    __shared__ float sm[NBG];
    sm[bg] = sum;
    __syncthreads();
#pragma unroll
    for (int o = NBG/2; o > 0; o >>= 1) {
        if (threadIdx.x < o) sm[threadIdx.x] += sm[threadIdx.x + o];
        __syncthreads();
    }
    if (threadIdx.x == 0)
        out[0] = sm[0] * (1.0f / ((float)(HW-1) * (float)NP * (float)B_));
}

extern "C" void kernel_launch(void* const* d_in, const int* in_sizes, int n_in,
                              void* d_out, int out_size) {
    const float* x   = (const float*)d_in[0];
    const float* cw  = (const float*)d_in[1];
    const int*   sel = (const int*)d_in[2];
    float* out = (float*)d_out;

    cudaFuncSetAttribute(gram_kernel,
                         cudaFuncAttributeMaxDynamicSharedMemorySize,
                         SMEM_FLOATS * sizeof(float));

    prep_kernel<<<C_, CH>>>(cw, sel);
    gram_kernel<<<NBG*S_, THREADS, SMEM_FLOATS * sizeof(float)>>>(x);
    reduce_kernel<<<1, NBG>>>(out);
}

// round 6
// speedup vs baseline: 1.1198x; 1.0417x over previous
#include <cuda_runtime.h>
#include <stdint.h>
#include <math.h>

// Problem shapes (fixed for this dataset entry)
#define B_    16
#define CH    512
#define HW    16384
#define C_    16              // selected classes
#define G_    32              // groups (CH/C_)
#define NP    120             // off-diagonal pairs
#define HNP   60              // pairs per thread-half
#define S_    2               // HW chunks per (b,g)
#define CHUNK (HW/S_)         // 8192
#define NBG   (B_*G_)         // 512
#define THREADS 256

#define SK        1024                  // floats per channel per stage
#define NSTAGES   (CHUNK/SK)            // 8
#define SMEM_FLOATS (2*C_*SK)           // 32768 floats = 128 KB

// Scratch (static __device__ — no allocations allowed)
__device__ int   d_src[CH];              // [k*C_+cls] -> source channel in x
__device__ float d_wgh[CH];              // [k*C_+cls] -> sigmoid(|w|)
__device__ float d_part[NBG*S_*NP];      // partial Gram sums

__device__ __forceinline__ void cp_async16(unsigned int saddr, const void* gptr) {
    asm volatile("cp.async.cg.shared.global [%0], [%1], 16;" :: "r"(saddr), "l"(gptr));
}
__device__ __forceinline__ void cp_commit() {
    asm volatile("cp.async.commit_group;");
}
template<int N>
__device__ __forceinline__ void cp_wait() {
    asm volatile("cp.async.wait_group %0;" :: "n"(N));
}
__device__ __forceinline__ unsigned int smem_u32(const void* p) {
    unsigned int a;
    asm("{ .reg .u64 t; cvta.to.shared.u64 t, %1; cvt.u32.u64 %0, t; }" : "=r"(a) : "l"(p));
    return a;
}
// packed dual-lane fp32 FMA: d.lo += a.lo*b.lo; d.hi += a.hi*b.hi
#define FMA2(d, a, b) \
    asm("fma.rn.f32x2 %0, %1, %2, %0;" : "+l"(d) : "l"(a), "l"(b))

// ---------------------------------------------------------------------------
// Kernel 1: rank-based top-G selection, 4-way parallel per class.
// Grid = C_*4 CTAs; CTA = (class, channel-quarter). 512 threads: 4 threads per
// channel, each comparing against a 128-wide slice of d. |w| compared as
// integer bits (monotone for non-negative floats); stable tie-break d < c.
// ---------------------------------------------------------------------------
__global__ void prep_kernel(const float* __restrict__ cw, const int* __restrict__ sel) {
    __shared__ unsigned int sbits[CH];
    __shared__ int part[128][4];
    int t = threadIdx.x;
    int cls_idx = blockIdx.x >> 2;        // 0..15
    int cq      = blockIdx.x & 3;         // channel quarter
    int cls = sel[cls_idx];

    sbits[t] = __float_as_uint(fabsf(cw[cls*CH + t]));
    __syncthreads();

    int c = cq*128 + (t >> 2);            // channel this thread helps rank
    int p = t & 3;                        // d-slice
    unsigned int mine = sbits[c];
    int cnt = 0;
#pragma unroll 8
    for (int dd = p*128; dd < p*128 + 128; dd++) {
        unsigned int o = sbits[dd];
        cnt += (o > mine) || (o == mine && dd < c);
    }
    part[t >> 2][p] = cnt;
    __syncthreads();

    if (t < 128) {
        int ch = cq*128 + t;
        int rank = part[t][0] + part[t][1] + part[t][2] + part[t][3];
        if (rank < G_) {
            float val = __uint_as_float(sbits[ch]);
            d_src[rank*C_ + cls_idx] = ch;
            d_wgh[rank*C_ + cls_idx] = 1.0f / (1.0f + expf(-val));
        }
    }
}

// ---------------------------------------------------------------------------
// Gram accumulate for one float4 (= 2 f32x2 lanes) per channel, pairs
// [QLO, QLO+60). Fully unrolled; constexpr-guarded.
// ---------------------------------------------------------------------------
template<int QLO>
__device__ __forceinline__ void accum60(unsigned long long* __restrict__ acc,
                                        const ulonglong2* __restrict__ v) {
    int q = 0;
#pragma unroll
    for (int i = 0; i < C_; i++) {
#pragma unroll
        for (int j = i+1; j < C_; j++) {
            if (q >= QLO && q < QLO + HNP) {
                FMA2(acc[q - QLO], v[i].x, v[j].x);
                FMA2(acc[q - QLO], v[i].y, v[j].y);
            }
            q++;
        }
    }
}

// ---------------------------------------------------------------------------
// Kernel 2: partial Gram per (b, g, chunk). cp.async double-buffered smem
// pipeline (2 x 64 KB stages). Pairs split across thread halves:
// warps 0-3 -> pairs 0..59, warps 4-7 -> pairs 60..119. Each half streams the
// full stage (2 float4-iters/thread). f32x2 packed FMA halves inst count.
// ---------------------------------------------------------------------------
extern __shared__ float sA[];   // [2][C_][SK]

__global__ void __launch_bounds__(THREADS, 1)
gram_kernel(const float* __restrict__ x) {
    int bid = blockIdx.x;                 // 0 .. NBG*S_-1
    int bg  = bid >> 1;                   // S_ == 2
    int s   = bid & (S_-1);
    int b   = bg / G_;
    int g   = bg % G_;
    int t   = threadIdx.x;

    __shared__ int soff[C_];
    if (t < C_)
        soff[t] = d_src[g*C_ + t] * (HW/4);  // channel offset in float4 units
    __syncthreads();

    const float4* base = (const float4*)x + ((size_t)b * CH) * (HW/4) + (size_t)s * (CHUNK/4);
    int off[C_];
#pragma unroll
    for (int i = 0; i < C_; i++) off[i] = soff[i];

    unsigned int sbase = smem_u32(sA);

    auto copy_stage = [&](int st, int buf) {
#pragma unroll
        for (int ch = 0; ch < C_; ch++) {
            unsigned int daddr = sbase + (unsigned int)(((buf*C_ + ch)*SK + 4*t) * 4);
            cp_async16(daddr, (const void*)(base + off[ch] + st*(SK/4) + t));
        }
        cp_commit();
    };

    int half = t >> 7;                    // 0: pairs 0..59, 1: pairs 60..119
    int kt   = t & 127;

    unsigned long long acc[HNP];
#pragma unroll
    for (int q = 0; q < HNP; q++) acc[q] = 0ull;

    copy_stage(0, 0);

    for (int st = 0; st < NSTAGES; st++) {
        __syncthreads();
        if (st + 1 < NSTAGES) { copy_stage(st + 1, (st + 1) & 1); cp_wait<1>(); }
        else                  { cp_wait<0>(); }
        __syncthreads();

        const ulonglong2* sp = (const ulonglong2*)(sA + ((st & 1) * C_) * SK);
#pragma unroll
        for (int it2 = 0; it2 < 2; it2++) {
            int k = kt + it2*128;         // float4 index within stage
            ulonglong2 v[C_];
#pragma unroll
            for (int i = 0; i < C_; i++) v[i] = sp[i*(SK/4) + k];
            if (half == 0) accum60<0>(acc, v);
            else           accum60<HNP>(acc, v);
        }
    }

    // collapse f32x2 lanes -> scalar
    float a[HNP];
#pragma unroll
    for (int q = 0; q < HNP; q++) {
        unsigned int lo, hi;
        asm("mov.b64 {%0, %1}, %2;" : "=r"(lo), "=r"(hi) : "l"(acc[q]));
        a[q] = __uint_as_float(lo) + __uint_as_float(hi);
    }
    // warp reduce
#pragma unroll
    for (int q = 0; q < HNP; q++) {
        float v = a[q];
#pragma unroll
        for (int o = 16; o > 0; o >>= 1)
            v += __shfl_down_sync(0xffffffffu, v, o);
        a[q] = v;
    }

    __syncthreads();
    float* red = sA;                      // reuse: [8][HNP]
    int warp = t >> 5, lane = t & 31;
    if (lane == 0) {
#pragma unroll
        for (int q = 0; q < HNP; q++) red[warp*HNP + q] = a[q];
    }
    __syncthreads();
    if (t < HNP) {                        // combine half0 (warps 0..3)
        float sum = red[0*HNP+t] + red[1*HNP+t] + red[2*HNP+t] + red[3*HNP+t];
        d_part[(size_t)bid*NP + t] = sum;
    } else if (t >= 64 && t < 64 + HNP) { // combine half1 (warps 4..7)
        int p = t - 64;
        float sum = red[4*HNP+p] + red[5*HNP+p] + red[6*HNP+p] + red[7*HNP+p];
        d_part[(size_t)bid*NP + HNP + p] = sum;
    }
}

// ---------------------------------------------------------------------------
// Kernel 3: fused combine + |.|*w_i*w_j + full reduction + normalization.
// ---------------------------------------------------------------------------
__global__ void reduce_kernel(float* __restrict__ out) {
    int bg = threadIdx.x;                 // 0..NBG-1
    int g  = bg % G_;
    const float* pa = d_part + (size_t)(2*bg)   * NP;
    const float* pb = d_part + (size_t)(2*bg+1) * NP;

    float w[C_];
#pragma unroll
    for (int i = 0; i < C_; i++) w[i] = d_wgh[g*C_ + i];

    float sum = 0.0f;
    int p = 0;
#pragma unroll
    for (int i = 0; i < C_; i++) {
#pragma unroll
        for (int j = i+1; j < C_; j++) {
            sum += fabsf(pa[p] + pb[p]) * (w[i] * w[j]);
            p++;
        }
    }

    __shared__ float sm[NBG];
    sm[bg] = sum;
    __syncthreads();
#pragma unroll
    for (int o = NBG/2; o > 0; o >>= 1) {
        if (threadIdx.x < o) sm[threadIdx.x] += sm[threadIdx.x + o];
        __syncthreads();
    }
    if (threadIdx.x == 0)
        out[0] = sm[0] * (1.0f / ((float)(HW-1) * (float)NP * (float)B_));
}

extern "C" void kernel_launch(void* const* d_in, const int* in_sizes, int n_in,
                              void* d_out, int out_size) {
    const float* x   = (const float*)d_in[0];
    const float* cw  = (const float*)d_in[1];
    const int*   sel = (const int*)d_in[2];
    float* out = (float*)d_out;

    cudaFuncSetAttribute(gram_kernel,
                         cudaFuncAttributeMaxDynamicSharedMemorySize,
                         SMEM_FLOATS * sizeof(float));

    prep_kernel<<<C_*4, CH>>>(cw, sel);
    gram_kernel<<<NBG*S_, THREADS, SMEM_FLOATS * sizeof(float)>>>(x);
    reduce_kernel<<<1, NBG>>>(out);
}